// round 10
// baseline (speedup 1.0000x reference)
#include <cuda_runtime.h>
#include <float.h>

#define L_SEQ 4096
#define N_TOTAL 512
#define WPB 8            // warps per block
#define TPB (WPB * 32)
#define PAD_MAX 4096     // P <= 4094
#define LP_MAX (L_SEQ + 2 * PAD_MAX)   // 12288 floats per batch
#define SMEM_BYTES (2 * LP_MAX * 4)    // two batches: 98304 bytes dynamic smem
#define MAX_B 64

__device__ int g_inv[N_TOTAL];
__device__ int g_P;
__device__ int g_ctr[MAX_B];   // one work counter per batch-pair

// Reset work counters, build inverse permutation, recover P.
__global__ void setup_kernel(const int* __restrict__ perm,
                             const int* __restrict__ off0,
                             const int* __restrict__ lout0,
                             int n_perm) {
    int j = threadIdx.x;
    if (j < MAX_B) g_ctr[j] = 0;
    if (j < n_perm) g_inv[perm[j]] = j;
    if (j == 0) {
        int d6  = off0[6] - off0[0];
        int pad = (lout0[0] - L_SEQ + d6) / 2;
        g_P = off0[0] + pad;
    }
}

// Dual-batch sliding-window conv: same tap schedule applied to two x arrays.
// Two independent FMA chains per output step -> 2-way ILP; index math shared.
template<int KS>
__device__ __forceinline__ void conv_lane2(
    const float* __restrict__ p0, const float* __restrict__ p1,
    int steps, int d, float bsv, const float* __restrict__ wk,
    float& mx0, int& cnt0, float& mx1, int& cnt1)
{
    if (steps <= 0) return;
    if (steps >= KS) {
        float y0[KS], y1[KS];
#pragma unroll
        for (int j = 0; j < KS - 1; j++) { y0[j] = p0[j * d]; y1[j] = p1[j * d]; }
        const float* pl0 = p0 + (KS - 1) * d;
        const float* pl1 = p1 + (KS - 1) * d;
        int i = 0;
        for (; i + KS <= steps; i += KS) {
#pragma unroll
            for (int u = 0; u < KS; u++) {
                y0[(u + KS - 1) % KS] = *pl0; pl0 += d;
                y1[(u + KS - 1) % KS] = *pl1; pl1 += d;
                float s0 = bsv, s1 = bsv;
#pragma unroll
                for (int k = 0; k < KS; k++) {
                    s0 = fmaf(wk[k], y0[(u + k) % KS], s0);
                    s1 = fmaf(wk[k], y1[(u + k) % KS], s1);
                }
                mx0 = fmaxf(mx0, s0); cnt0 += (s0 > 0.0f);
                mx1 = fmaxf(mx1, s1); cnt1 += (s1 > 0.0f);
            }
        }
        for (; i < steps; i++) {
            const float* q0 = p0 + i * d;
            const float* q1 = p1 + i * d;
            float s0 = bsv, s1 = bsv;
#pragma unroll
            for (int k = 0; k < KS; k++) {
                s0 = fmaf(wk[k], q0[k * d], s0);
                s1 = fmaf(wk[k], q1[k * d], s1);
            }
            mx0 = fmaxf(mx0, s0); cnt0 += (s0 > 0.0f);
            mx1 = fmaxf(mx1, s1); cnt1 += (s1 > 0.0f);
        }
    } else {
        for (int i = 0; i < steps; i++) {
            const float* q0 = p0 + i * d;
            const float* q1 = p1 + i * d;
            float s0 = bsv, s1 = bsv;
#pragma unroll
            for (int k = 0; k < KS; k++) {
                s0 = fmaf(wk[k], q0[k * d], s0);
                s1 = fmaf(wk[k], q1[k * d], s1);
            }
            mx0 = fmaxf(mx0, s0); cnt0 += (s0 > 0.0f);
            mx1 = fmaxf(mx1, s1); cnt1 += (s1 > 0.0f);
        }
    }
}

template<int KS>
__device__ __forceinline__ void run_group(
    const float* __restrict__ sx0, const float* __restrict__ sx1,
    const float* __restrict__ w, const float* __restrict__ bias,
    const int*  __restrict__ off, const int* __restrict__ lout,
    float* __restrict__ out, int gi, int base,
    int b0, int b1, int b1_valid, int stride)
{
    const int lane = threadIdx.x & 31;

    float wk[KS];
#pragma unroll
    for (int k = 0; k < KS; k++) wk[k] = __ldg(&w[gi * KS + k]);
    const int   o0  = __ldg(&off[gi * KS]);           // padded-array base for tap 0
    const int   d   = __ldg(&off[gi * KS + 1]) - o0;  // dilation
    const float bsv = __ldg(&bias[gi]);
    const int   lo  = __ldg(&lout[gi]);

    float mx0 = -FLT_MAX, mx1 = -FLT_MAX;
    int   cnt0 = 0, cnt1 = 0;
    const float* px0 = sx0 + o0;
    const float* px1 = sx1 + o0;

    if (d < 32) {
        // lane -> (residue r, chunk g); uniform odd chunk size => conflict-free banks
        const int r = lane % d;
        const int g = lane / d;
        const int Mmax = (lo + d - 1) / d;
        const int Gmin = 32 / d;
        int mc = (Mmax + Gmin - 1) / Gmin;
        mc |= 1;                                   // round up to odd
        const int Mr = (r < lo) ? (lo - r + d - 1) / d : 0;
        int m0 = g * mc;
        int m1 = m0 + mc; if (m1 > Mr) m1 = Mr;
        if (m0 < m1)
            conv_lane2<KS>(px0 + r + d * m0, px1 + r + d * m0,
                           m1 - m0, d, bsv, wk, mx0, cnt0, mx1, cnt1);
    } else {
        // lanes = consecutive residues (consecutive addresses: conflict-free)
        for (int rb = 0; rb < d; rb += 32) {
            const int r = rb + lane;
            if (r < d) {
                const int Mr = (r < lo) ? (lo - r + d - 1) / d : 0;
                conv_lane2<KS>(px0 + r, px1 + r, Mr, d, bsv, wk,
                               mx0, cnt0, mx1, cnt1);
            }
        }
    }

    // warp reductions
#pragma unroll
    for (int o = 16; o; o >>= 1) {
        mx0  = fmaxf(mx0, __shfl_xor_sync(0xffffffffu, mx0, o));
        mx1  = fmaxf(mx1, __shfl_xor_sync(0xffffffffu, mx1, o));
        cnt0 += __shfl_xor_sync(0xffffffffu, cnt0, o);
        cnt1 += __shfl_xor_sync(0xffffffffu, cnt1, o);
    }

    if (lane == 0) {
        int col = g_inv[base + gi];
        float inv_lo = 1.0f / (float)lo;
        out[b0 * stride + 2 * col]     = mx0;
        out[b0 * stride + 2 * col + 1] = (float)cnt0 * inv_lo;
        if (b1_valid) {
            out[b1 * stride + 2 * col]     = mx1;
            out[b1 * stride + 2 * col + 1] = (float)cnt1 * inv_lo;
        }
    }
}

__global__ __launch_bounds__(TPB)
void rocket_all_kernel(
    const float* __restrict__ x, int B,
    const float* __restrict__ w0, const float* __restrict__ b0p,
    const int*  __restrict__ off0, const int* __restrict__ lout0, int n0,
    const float* __restrict__ w1, const float* __restrict__ b1p,
    const int*  __restrict__ off1, const int* __restrict__ lout1, int n1,
    const float* __restrict__ w2, const float* __restrict__ b2p,
    const int*  __restrict__ off2, const int* __restrict__ lout2, int n2,
    float* __restrict__ out, int stride)
{
    extern __shared__ float smem[];
    float* sx0 = smem;
    float* sx1 = smem + LP_MAX;

    const int pb = blockIdx.y;            // batch pair index
    const int b0 = 2 * pb;
    const int b1 = 2 * pb + 1;
    const int b1_valid = (b1 < B);
    const int P = g_P;
    const int N = n0 + n1 + n2;
    const int tid = threadIdx.x;

    // zero pad regions of both staging arrays
    for (int i = tid; i < P; i += TPB) {
        sx0[i]             = 0.0f;
        sx0[P + L_SEQ + i] = 0.0f;
        sx1[i]             = 0.0f;
        sx1[P + L_SEQ + i] = 0.0f;
    }
    // stage x[b0] and x[b1] (P even => float2-aligned)
    {
        const float2* xa = (const float2*)(x + (size_t)b0 * L_SEQ);
        const float2* xb = (const float2*)(x + (size_t)(b1_valid ? b1 : b0) * L_SEQ);
        float2* d0 = (float2*)(sx0 + P);
        float2* d1 = (float2*)(sx1 + P);
        for (int i = tid; i < L_SEQ / 2; i += TPB) {
            d0[i] = xa[i];
            d1[i] = xb[i];
        }
    }
    __syncthreads();

    const int lane = threadIdx.x & 31;

    // warp-granular work stealing over kernels for this batch pair
    for (;;) {
        int item = 0;
        if (lane == 0) item = atomicAdd(&g_ctr[pb], 1);
        item = __shfl_sync(0xffffffffu, item, 0);
        if (item >= N) break;

        if (item < n0) {
            run_group<7>(sx0, sx1, w0, b0p, off0, lout0, out, item, 0,
                         b0, b1, b1_valid, stride);
        } else if (item < n0 + n1) {
            run_group<9>(sx0, sx1, w1, b1p, off1, lout1, out, item - n0, n0,
                         b0, b1, b1_valid, stride);
        } else {
            run_group<11>(sx0, sx1, w2, b2p, off2, lout2, out, item - n0 - n1, n0 + n1,
                          b0, b1, b1_valid, stride);
        }
    }
}

extern "C" void kernel_launch(void* const* d_in, const int* in_sizes, int n_in,
                              void* d_out, int out_size) {
    // Dict order:      x, perm, P, w0,b0,off0,lout0, w1,b1,off1,lout1, w2,b2,off2,lout2
    // Signature order: x, w0,b0,off0,lout0, w1,b1,off1,lout1, w2,b2,off2,lout2, perm, P
    int ix, iperm, ig0, ig1, ig2;
    if (n_in >= 3 && in_sizes[1] == N_TOTAL && in_sizes[2] == 1) {
        ix = 0; iperm = 1; ig0 = 3; ig1 = 7; ig2 = 11;
    } else {
        ix = 0; ig0 = 1; ig1 = 5; ig2 = 9; iperm = 13;
    }

    const float* x     = (const float*)d_in[ix];
    const int*   perm  = (const int*)  d_in[iperm];

    const float* w0    = (const float*)d_in[ig0 + 0];
    const float* b0    = (const float*)d_in[ig0 + 1];
    const int*   off0  = (const int*)  d_in[ig0 + 2];
    const int*   lout0 = (const int*)  d_in[ig0 + 3];
    const float* w1    = (const float*)d_in[ig1 + 0];
    const float* b1    = (const float*)d_in[ig1 + 1];
    const int*   off1  = (const int*)  d_in[ig1 + 2];
    const int*   lout1 = (const int*)  d_in[ig1 + 3];
    const float* w2    = (const float*)d_in[ig2 + 0];
    const float* b2    = (const float*)d_in[ig2 + 1];
    const int*   off2  = (const int*)  d_in[ig2 + 2];
    const int*   lout2 = (const int*)  d_in[ig2 + 3];

    const int n0 = in_sizes[ig0 + 1];
    const int n1 = in_sizes[ig1 + 1];
    const int n2 = in_sizes[ig2 + 1];
    const int B  = in_sizes[ix] / L_SEQ;
    const int N  = n0 + n1 + n2;
    const int stride = 2 * N;

    static bool attr_set = false;
    if (!attr_set) {
        cudaFuncSetAttribute(rocket_all_kernel,
                             cudaFuncAttributeMaxDynamicSharedMemorySize, SMEM_BYTES);
        attr_set = true;
    }

    setup_kernel<<<1, N_TOTAL>>>(perm, off0, lout0, in_sizes[iperm]);

    const int NP = (B + 1) / 2;           // batch pairs
    // 2 blocks/SM * 148 SMs = 296 resident blocks
    int bpb = 296 / (NP > 0 ? NP : 1);
    if (bpb < 1) bpb = 1;
    int max_bpb = (N + WPB - 1) / WPB;
    if (bpb > max_bpb) bpb = max_bpb;

    dim3 grid(bpb, NP);
    rocket_all_kernel<<<grid, TPB, SMEM_BYTES>>>(
        x, B,
        w0, b0, off0, lout0, n0,
        w1, b1, off1, lout1, n1,
        w2, b2, off2, lout2, n2,
        (float*)d_out, stride);
}

// round 11
// speedup vs baseline: 1.1429x; 1.1429x over previous
#include <cuda_runtime.h>
#include <float.h>

#define L_SEQ 4096
#define N_TOTAL 512
#define WPB 8            // warps per block
#define TPB (WPB * 32)
#define PAD_MAX 4096     // P <= 4094
#define LP_MAX (L_SEQ + 2 * PAD_MAX)   // 12288 floats = 48KB static shared (exact limit)
#define MAX_B 64

__device__ int g_inv[N_TOTAL];
__device__ int g_P;
__device__ int g_ctr[MAX_B];
__device__ int g_order[N_TOTAL];   // items sorted by descending lout (LPT schedule)

// Reset counters, build inverse permutation, recover P, build LPT order.
__global__ void setup_kernel(const int* __restrict__ perm,
                             const int* __restrict__ off0,
                             const int* __restrict__ lout0,
                             const int* __restrict__ lout1,
                             const int* __restrict__ lout2,
                             int n0, int n1, int n_perm) {
    int j = threadIdx.x;
    if (j < MAX_B) g_ctr[j] = 0;
    if (j < n_perm) g_inv[perm[j]] = j;
    if (j == 0) {
        int d6  = off0[6] - off0[0];
        int pad = (lout0[0] - L_SEQ + d6) / 2;
        g_P = off0[0] + pad;
    }
    // LPT: rank item j by count of items with (lout greater) or (equal, smaller idx)
    if (j < n_perm) {
        int lo_j = (j < n0) ? lout0[j] : (j < n0 + n1) ? lout1[j - n0] : lout2[j - n0 - n1];
        int rank = 0;
        for (int i = 0; i < n_perm; i++) {
            int lo_i = (i < n0) ? lout0[i] : (i < n0 + n1) ? lout1[i - n0] : lout2[i - n0 - n1];
            rank += (lo_i > lo_j) || (lo_i == lo_j && i < j);
        }
        g_order[rank] = j;
    }
}

// Sliding-window 1D conv along m for one lane: s_m = bsv + sum_k wk[k]*p[(m+k)*d].
// Window rotation fully unrolled; loads use independent addresses pl[u*d] (MLP).
template<int KS>
__device__ __forceinline__ void conv_lane(
    const float* __restrict__ p, int steps, int d, float bsv,
    const float* __restrict__ wk, float& mx, int& cnt)
{
    if (steps <= 0) return;
    if (steps >= KS) {
        float y[KS];
#pragma unroll
        for (int j = 0; j < KS - 1; j++) y[j] = p[j * d];
        const float* pl = p + (KS - 1) * d;
        int i = 0;
        for (; i + KS <= steps; i += KS) {
#pragma unroll
            for (int u = 0; u < KS; u++) {
                y[(u + KS - 1) % KS] = pl[u * d];
                float s = bsv;
#pragma unroll
                for (int k = 0; k < KS; k++)
                    s = fmaf(wk[k], y[(u + k) % KS], s);
                mx = fmaxf(mx, s);
                cnt += (s > 0.0f);
            }
            pl += KS * d;
        }
        for (; i < steps; i++) {
            const float* q = p + i * d;
            float s = bsv;
#pragma unroll
            for (int k = 0; k < KS; k++) s = fmaf(wk[k], q[k * d], s);
            mx = fmaxf(mx, s);
            cnt += (s > 0.0f);
        }
    } else {
        for (int i = 0; i < steps; i++) {
            const float* q = p + i * d;
            float s = bsv;
#pragma unroll
            for (int k = 0; k < KS; k++) s = fmaf(wk[k], q[k * d], s);
            mx = fmaxf(mx, s);
            cnt += (s > 0.0f);
        }
    }
}

template<int KS>
__device__ __forceinline__ void run_group(
    const float* __restrict__ sx,          // zero-padded: x lives at [P, P+L)
    const float* __restrict__ w, const float* __restrict__ bias,
    const int*  __restrict__ off, const int* __restrict__ lout,
    float* __restrict__ out, int gi, int base, int b, int stride)
{
    const int lane = threadIdx.x & 31;

    float wk[KS];
#pragma unroll
    for (int k = 0; k < KS; k++) wk[k] = __ldg(&w[gi * KS + k]);
    const int   o0  = __ldg(&off[gi * KS]);           // padded-array base for tap 0
    const int   d   = __ldg(&off[gi * KS + 1]) - o0;  // dilation
    const float bsv = __ldg(&bias[gi]);
    const int   lo  = __ldg(&lout[gi]);

    float mx  = -FLT_MAX;
    int   cnt = 0;
    const float* px = sx + o0;

    if (d < 32) {
        // lane -> (residue r, chunk g); uniform odd chunk size => conflict-free banks
        const int r = lane % d;
        const int g = lane / d;
        const int Mmax = (lo + d - 1) / d;
        const int Gmin = 32 / d;
        int mc = (Mmax + Gmin - 1) / Gmin;
        mc |= 1;                                   // round up to odd
        const int Mr = (r < lo) ? (lo - r + d - 1) / d : 0;
        int m0 = g * mc;
        int m1 = m0 + mc; if (m1 > Mr) m1 = Mr;
        if (m0 < m1)
            conv_lane<KS>(px + r + d * m0, m1 - m0, d, bsv, wk, mx, cnt);
    } else {
        // lanes = consecutive residues (consecutive addresses: conflict-free)
        for (int rb = 0; rb < d; rb += 32) {
            const int r = rb + lane;
            if (r < d) {
                const int Mr = (r < lo) ? (lo - r + d - 1) / d : 0;
                conv_lane<KS>(px + r, Mr, d, bsv, wk, mx, cnt);
            }
        }
    }

    // warp reductions
#pragma unroll
    for (int o = 16; o; o >>= 1) {
        mx   = fmaxf(mx, __shfl_xor_sync(0xffffffffu, mx, o));
        cnt += __shfl_xor_sync(0xffffffffu, cnt, o);
    }

    if (lane == 0) {
        int col = g_inv[base + gi];
        out[b * stride + 2 * col]     = mx;
        out[b * stride + 2 * col + 1] = (float)cnt / (float)lo;
    }
}

__global__ __launch_bounds__(TPB)
void rocket_all_kernel(
    const float* __restrict__ x,
    const float* __restrict__ w0, const float* __restrict__ b0,
    const int*  __restrict__ off0, const int* __restrict__ lout0, int n0,
    const float* __restrict__ w1, const float* __restrict__ b1,
    const int*  __restrict__ off1, const int* __restrict__ lout1, int n1,
    const float* __restrict__ w2, const float* __restrict__ b2,
    const int*  __restrict__ off2, const int* __restrict__ lout2, int n2,
    float* __restrict__ out, int stride)
{
    __shared__ float sx[LP_MAX];
    const int b = blockIdx.y;
    const int P = g_P;
    const int N = n0 + n1 + n2;

    // zero pad regions [0,P) and [P+L, P+L+P)
    for (int i = threadIdx.x; i < P; i += TPB) {
        sx[i]             = 0.0f;
        sx[P + L_SEQ + i] = 0.0f;
    }
    // stage x[b] into sx[P .. P+L): P even => float2-aligned
    {
        const float2* xb2 = (const float2*)(x + (size_t)b * L_SEQ);
        float2* dst = (float2*)(sx + P);
        for (int i = threadIdx.x; i < L_SEQ / 2; i += TPB)
            dst[i] = xb2[i];
    }
    __syncthreads();

    const int lane = threadIdx.x & 31;

    // warp-granular work stealing in LPT (longest-first) order
    for (;;) {
        int slot = 0;
        if (lane == 0) slot = atomicAdd(&g_ctr[b], 1);
        slot = __shfl_sync(0xffffffffu, slot, 0);
        if (slot >= N) break;
        const int item = g_order[slot];

        if (item < n0) {
            run_group<7>(sx, w0, b0, off0, lout0, out, item, 0, b, stride);
        } else if (item < n0 + n1) {
            run_group<9>(sx, w1, b1, off1, lout1, out, item - n0, n0, b, stride);
        } else {
            run_group<11>(sx, w2, b2, off2, lout2, out, item - n0 - n1, n0 + n1, b, stride);
        }
    }
}

extern "C" void kernel_launch(void* const* d_in, const int* in_sizes, int n_in,
                              void* d_out, int out_size) {
    // Dict order:      x, perm, P, w0,b0,off0,lout0, w1,b1,off1,lout1, w2,b2,off2,lout2
    // Signature order: x, w0,b0,off0,lout0, w1,b1,off1,lout1, w2,b2,off2,lout2, perm, P
    int ix, iperm, ig0, ig1, ig2;
    if (n_in >= 3 && in_sizes[1] == N_TOTAL && in_sizes[2] == 1) {
        ix = 0; iperm = 1; ig0 = 3; ig1 = 7; ig2 = 11;
    } else {
        ix = 0; ig0 = 1; ig1 = 5; ig2 = 9; iperm = 13;
    }

    const float* x     = (const float*)d_in[ix];
    const int*   perm  = (const int*)  d_in[iperm];

    const float* w0    = (const float*)d_in[ig0 + 0];
    const float* b0    = (const float*)d_in[ig0 + 1];
    const int*   off0  = (const int*)  d_in[ig0 + 2];
    const int*   lout0 = (const int*)  d_in[ig0 + 3];
    const float* w1    = (const float*)d_in[ig1 + 0];
    const float* b1    = (const float*)d_in[ig1 + 1];
    const int*   off1  = (const int*)  d_in[ig1 + 2];
    const int*   lout1 = (const int*)  d_in[ig1 + 3];
    const float* w2    = (const float*)d_in[ig2 + 0];
    const float* b2    = (const float*)d_in[ig2 + 1];
    const int*   off2  = (const int*)  d_in[ig2 + 2];
    const int*   lout2 = (const int*)  d_in[ig2 + 3];

    const int n0 = in_sizes[ig0 + 1];
    const int n1 = in_sizes[ig1 + 1];
    const int n2 = in_sizes[ig2 + 1];
    const int B  = in_sizes[ix] / L_SEQ;
    const int N  = n0 + n1 + n2;
    const int stride = 2 * N;

    setup_kernel<<<1, N_TOTAL>>>(perm, off0, lout0, lout1, lout2, n0, n1,
                                 in_sizes[iperm]);

    // persistent balanced grid: ~4 blocks/SM * 148 SMs
    int bpb = 592 / (B > 0 ? B : 1);
    if (bpb < 1) bpb = 1;
    int max_bpb = (N + WPB - 1) / WPB;
    if (bpb > max_bpb) bpb = max_bpb;

    dim3 grid(bpb, B);
    rocket_all_kernel<<<grid, TPB>>>(
        x,
        w0, b0, off0, lout0, n0,
        w1, b1, off1, lout1, n1,
        w2, b2, off2, lout2, n2,
        (float*)d_out, stride);
}

// round 12
// speedup vs baseline: 1.5879x; 1.3894x over previous
#include <cuda_runtime.h>
#include <float.h>

#define L_SEQ 4096
#define N_TOTAL 512
#define WPB 8            // warps per block
#define TPB (WPB * 32)
#define PAD_MAX 4096     // P <= 4094
#define LP_MAX (L_SEQ + 2 * PAD_MAX)   // 12288 floats = 48KB static shared
#define MAX_B 64

__device__ int g_inv[N_TOTAL];
__device__ int g_P;
__device__ int g_ctr[MAX_B];

// Reset work counters, build inverse permutation, recover P. Cheap O(N).
__global__ void setup_kernel(const int* __restrict__ perm,
                             const int* __restrict__ off0,
                             const int* __restrict__ lout0,
                             int n_perm) {
    int j = threadIdx.x;
    if (j < MAX_B) g_ctr[j] = 0;
    if (j < n_perm) g_inv[perm[j]] = j;
    if (j == 0) {
        int d6  = off0[6] - off0[0];
        int pad = (lout0[0] - L_SEQ + d6) / 2;
        g_P = off0[0] + pad;
    }
}

// ---- f32x2 packed helpers (sm_100a) ----
typedef unsigned long long ull;
__device__ __forceinline__ ull pack2(float lo, float hi) {
    ull r; asm("mov.b64 %0, {%1,%2};" : "=l"(r) : "f"(lo), "f"(hi)); return r;
}
__device__ __forceinline__ void unpack2(ull v, float& lo, float& hi) {
    asm("mov.b64 {%0,%1}, %2;" : "=f"(lo), "=f"(hi) : "l"(v));
}
__device__ __forceinline__ ull fma2(ull a, ull b, ull c) {
    ull d; asm("fma.rn.f32x2 %0, %1, %2, %3;" : "=l"(d) : "l"(a), "l"(b), "l"(c)); return d;
}

// Packed sliding-window conv: outputs s_m = bsv + sum_k wk[k]*p[(m+k)*d],
// m in [0, steps), two outputs per f32x2 FMA chain. Window rotation by 2 over
// KS packed regs (KS odd -> period KS, fully unrolled => rename-only).
// All loads stay within the legal tap range (max index = steps-1 + KS-1 taps).
template<int KS>
__device__ __forceinline__ void conv_lane(
    const float* __restrict__ p, int steps, int d, float bsv,
    const float* __restrict__ wk, float& mx, int& cnt)
{
    if (steps <= 0) return;
    int i = 0;
    if (steps >= 2 * KS) {
        ull w2[KS];
#pragma unroll
        for (int k = 0; k < KS; k++) w2[k] = pack2(wk[k], wk[k]);
        const ull b2 = pack2(bsv, bsv);

        // prologue: y_0..y_{KS-2} -> packs y2[0..KS-3], carry c = y_{KS-2}
        float yp[KS - 1];
#pragma unroll
        for (int j = 0; j < KS - 1; j++) yp[j] = p[j * d];
        ull y2[KS];
#pragma unroll
        for (int j = 0; j < KS - 2; j++) y2[j] = pack2(yp[j], yp[j + 1]);
        float c = yp[KS - 2];
        const float* pl = p + (KS - 1) * d;

        for (; i + 2 * KS <= steps; i += 2 * KS) {
#pragma unroll
            for (int u = 0; u < KS; u++) {
                // loads complete the window for pair (i+2u, i+2u+1)
                float n0 = pl[2 * u * d];
                float n1 = pl[2 * u * d + d];
                y2[(2 * u + KS - 2) % KS] = pack2(c, n0);
                y2[(2 * u + KS - 1) % KS] = pack2(n0, n1);
                c = n1;
                ull s2 = b2;
#pragma unroll
                for (int k = 0; k < KS; k++)
                    s2 = fma2(w2[k], y2[(2 * u + k) % KS], s2);
                float s0, s1; unpack2(s2, s0, s1);
                mx = fmaxf(mx, fmaxf(s0, s1));
                cnt += (s0 > 0.0f);
                cnt += (s1 > 0.0f);
            }
            pl += 2 * KS * d;
        }
    }
    // tail / short runs: direct taps
    for (; i < steps; i++) {
        const float* q = p + i * d;
        float s = bsv;
#pragma unroll
        for (int k = 0; k < KS; k++) s = fmaf(wk[k], q[k * d], s);
        mx = fmaxf(mx, s);
        cnt += (s > 0.0f);
    }
}

template<int KS>
__device__ __forceinline__ void run_group(
    const float* __restrict__ sx,          // zero-padded: x lives at [P, P+L)
    const float* __restrict__ w, const float* __restrict__ bias,
    const int*  __restrict__ off, const int* __restrict__ lout,
    float* __restrict__ out, int gi, int base, int b, int stride)
{
    const int lane = threadIdx.x & 31;

    float wk[KS];
#pragma unroll
    for (int k = 0; k < KS; k++) wk[k] = __ldg(&w[gi * KS + k]);
    const int   o0  = __ldg(&off[gi * KS]);           // padded-array base for tap 0
    const int   d   = __ldg(&off[gi * KS + 1]) - o0;  // dilation
    const float bsv = __ldg(&bias[gi]);
    const int   lo  = __ldg(&lout[gi]);

    float mx  = -FLT_MAX;
    int   cnt = 0;
    const float* px = sx + o0;

    if (d < 32) {
        // lane -> (residue r, chunk g); uniform odd chunk size => conflict-free banks
        const int r = lane % d;
        const int g = lane / d;
        const int Mmax = (lo + d - 1) / d;
        const int Gmin = 32 / d;
        int mc = (Mmax + Gmin - 1) / Gmin;
        mc |= 1;                                   // round up to odd
        const int Mr = (r < lo) ? (lo - r + d - 1) / d : 0;
        int m0 = g * mc;
        int m1 = m0 + mc; if (m1 > Mr) m1 = Mr;
        if (m0 < m1)
            conv_lane<KS>(px + r + d * m0, m1 - m0, d, bsv, wk, mx, cnt);
    } else {
        // lanes = consecutive residues (consecutive addresses: conflict-free)
        for (int rb = 0; rb < d; rb += 32) {
            const int r = rb + lane;
            if (r < d) {
                const int Mr = (r < lo) ? (lo - r + d - 1) / d : 0;
                conv_lane<KS>(px + r, Mr, d, bsv, wk, mx, cnt);
            }
        }
    }

    // warp reductions
#pragma unroll
    for (int o = 16; o; o >>= 1) {
        mx   = fmaxf(mx, __shfl_xor_sync(0xffffffffu, mx, o));
        cnt += __shfl_xor_sync(0xffffffffu, cnt, o);
    }

    if (lane == 0) {
        int col = g_inv[base + gi];
        out[b * stride + 2 * col]     = mx;
        out[b * stride + 2 * col + 1] = (float)cnt / (float)lo;
    }
}

__global__ __launch_bounds__(TPB)
void rocket_all_kernel(
    const float* __restrict__ x,
    const float* __restrict__ w0, const float* __restrict__ b0,
    const int*  __restrict__ off0, const int* __restrict__ lout0, int n0,
    const float* __restrict__ w1, const float* __restrict__ b1,
    const int*  __restrict__ off1, const int* __restrict__ lout1, int n1,
    const float* __restrict__ w2, const float* __restrict__ b2,
    const int*  __restrict__ off2, const int* __restrict__ lout2, int n2,
    float* __restrict__ out, int stride)
{
    __shared__ float sx[LP_MAX];
    const int b = blockIdx.y;
    const int P = g_P;
    const int N = n0 + n1 + n2;

    // zero pad regions [0,P) and [P+L, P+L+P)
    for (int i = threadIdx.x; i < P; i += TPB) {
        sx[i]             = 0.0f;
        sx[P + L_SEQ + i] = 0.0f;
    }
    // stage x[b] into sx[P .. P+L): P even => float2-aligned
    {
        const float2* xb2 = (const float2*)(x + (size_t)b * L_SEQ);
        float2* dst = (float2*)(sx + P);
        for (int i = threadIdx.x; i < L_SEQ / 2; i += TPB)
            dst[i] = xb2[i];
    }
    __syncthreads();

    const int lane = threadIdx.x & 31;

    // warp-granular work stealing over kernels for this batch
    for (;;) {
        int item = 0;
        if (lane == 0) item = atomicAdd(&g_ctr[b], 1);
        item = __shfl_sync(0xffffffffu, item, 0);
        if (item >= N) break;

        if (item < n0) {
            run_group<7>(sx, w0, b0, off0, lout0, out, item, 0, b, stride);
        } else if (item < n0 + n1) {
            run_group<9>(sx, w1, b1, off1, lout1, out, item - n0, n0, b, stride);
        } else {
            run_group<11>(sx, w2, b2, off2, lout2, out, item - n0 - n1, n0 + n1, b, stride);
        }
    }
}

extern "C" void kernel_launch(void* const* d_in, const int* in_sizes, int n_in,
                              void* d_out, int out_size) {
    // Dict order:      x, perm, P, w0,b0,off0,lout0, w1,b1,off1,lout1, w2,b2,off2,lout2
    // Signature order: x, w0,b0,off0,lout0, w1,b1,off1,lout1, w2,b2,off2,lout2, perm, P
    int ix, iperm, ig0, ig1, ig2;
    if (n_in >= 3 && in_sizes[1] == N_TOTAL && in_sizes[2] == 1) {
        ix = 0; iperm = 1; ig0 = 3; ig1 = 7; ig2 = 11;
    } else {
        ix = 0; ig0 = 1; ig1 = 5; ig2 = 9; iperm = 13;
    }

    const float* x     = (const float*)d_in[ix];
    const int*   perm  = (const int*)  d_in[iperm];

    const float* w0    = (const float*)d_in[ig0 + 0];
    const float* b0    = (const float*)d_in[ig0 + 1];
    const int*   off0  = (const int*)  d_in[ig0 + 2];
    const int*   lout0 = (const int*)  d_in[ig0 + 3];
    const float* w1    = (const float*)d_in[ig1 + 0];
    const float* b1    = (const float*)d_in[ig1 + 1];
    const int*   off1  = (const int*)  d_in[ig1 + 2];
    const int*   lout1 = (const int*)  d_in[ig1 + 3];
    const float* w2    = (const float*)d_in[ig2 + 0];
    const float* b2    = (const float*)d_in[ig2 + 1];
    const int*   off2  = (const int*)  d_in[ig2 + 2];
    const int*   lout2 = (const int*)  d_in[ig2 + 3];

    const int n0 = in_sizes[ig0 + 1];
    const int n1 = in_sizes[ig1 + 1];
    const int n2 = in_sizes[ig2 + 1];
    const int B  = in_sizes[ix] / L_SEQ;
    const int N  = n0 + n1 + n2;
    const int stride = 2 * N;

    setup_kernel<<<1, N_TOTAL>>>(perm, off0, lout0, in_sizes[iperm]);

    // persistent balanced grid: ~4 blocks/SM * 148 SMs
    int bpb = 592 / (B > 0 ? B : 1);
    if (bpb < 1) bpb = 1;
    int max_bpb = (N + WPB - 1) / WPB;
    if (bpb > max_bpb) bpb = max_bpb;

    dim3 grid(bpb, B);
    rocket_all_kernel<<<grid, TPB>>>(
        x,
        w0, b0, off0, lout0, n0,
        w1, b1, off1, lout1, n1,
        w2, b2, off2, lout2, n2,
        (float*)d_out, stride);
}